// round 14
// baseline (speedup 1.0000x reference)
#include <cuda_runtime.h>
#include <math.h>

#define H 256

#define BM 64
#define BJ 64
#define KC 16

#define HMAX_ROWS 32768
#define LEAF_N    262144
#define N_TOTAL   299593

// Scratch (device globals -- no allocation allowed)
__device__ float g_enc[(size_t)N_TOTAL * H];          // encoder outputs per tree node
__device__ float g_el [(size_t)LEAF_N  * H];          // left-LSTM final hidden
__device__ float g_er [(size_t)LEAF_N  * H];          // right-LSTM final hidden
__device__ float g_h[2][2][(size_t)HMAX_ROWS * H];    // [side][ping] hidden state
__device__ float g_c[2][2][(size_t)HMAX_ROWS * H];    // [side][ping] cell state

__device__ __forceinline__ float sigm(float x) { return 1.0f / (1.0f + expf(-x)); }

// ---- packed fp32x2 helpers (sm_103a FFMA2 path, PTX-only) ----
__device__ __forceinline__ unsigned long long pack2(float lo, float hi) {
    unsigned long long r;
    asm("mov.b64 %0, {%1, %2};" : "=l"(r)
        : "r"(__float_as_uint(lo)), "r"(__float_as_uint(hi)));
    return r;
}
__device__ __forceinline__ void unpack2(unsigned long long v, float& lo, float& hi) {
    unsigned int a, b;
    asm("mov.b64 {%0, %1}, %2;" : "=r"(a), "=r"(b) : "l"(v));
    lo = __uint_as_float(a);
    hi = __uint_as_float(b);
}
#define FFMA2(acc, a, b) \
    asm("fma.rn.f32x2 %0, %1, %2, %0;" : "+l"(acc) : "l"(a), "l"(b))

// One LSTM step for both the left (z=0) and right (z=1) chains.
// gates[n,1024] = X[n,256] @ Wih^T (+ Hprev[n,256] @ Whh^T) + bih + bhh
// X rows come from node_init (xsrc=0) or g_enc (xsrc=1) at row = xoff + m*xstr.
__global__ __launch_bounds__(256)
void lstm_step_kernel(
    const float* __restrict__ node_init,
    const float* __restrict__ Wih_l, const float* __restrict__ Whh_l,
    const float* __restrict__ bih_l, const float* __restrict__ bhh_l,
    const float* __restrict__ Wih_r, const float* __restrict__ Whh_r,
    const float* __restrict__ bih_r, const float* __restrict__ bhh_r,
    int n, int first, int last, int pp,
    int xsrc_l, long long xoff_l, int xstr_l,
    int xsrc_r, long long xoff_r, int xstr_r)
{
    const int side = blockIdx.z;
    const float* Wih = side ? Wih_r : Wih_l;
    const float* Whh = side ? Whh_r : Whh_l;
    const float* bih = side ? bih_r : bih_l;
    const float* bhh = side ? bhh_r : bhh_l;
    const int       xsrc = side ? xsrc_r : xsrc_l;
    const long long xoff = side ? xoff_r : xoff_l;
    const int       xstr = side ? xstr_r : xstr_l;

    const float* xbase = xsrc ? g_enc : node_init;
    const float* h_in  = g_h[side][pp];
    const float* c_in  = g_c[side][pp];
    float* h_out = last ? (side ? g_er : g_el) : g_h[side][pp ^ 1];
    float* c_out = g_c[side][pp ^ 1];

    __shared__ float As[BM][KC + 1];
    __shared__ float Hs[BM][KC + 1];
    __shared__ float Wi[4][BJ][KC + 1];
    __shared__ float Wh[4][BJ][KC + 1];

    const int tid = threadIdx.x;
    const int ty = tid >> 5, tx = tid & 31;
    const int m0 = blockIdx.x * BM;
    const int jb = blockIdx.y * BJ;

    // packed accumulators: lane pair (j = jb+tx, j = jb+tx+32)
    unsigned long long acc[8][4];
#pragma unroll
    for (int r = 0; r < 8; r++)
#pragma unroll
        for (int g = 0; g < 4; g++) acc[r][g] = 0ull;

    for (int kc = 0; kc < H; kc += KC) {
        // --- stage A/H tiles ---
#pragma unroll
        for (int i = tid; i < BM * KC; i += 256) {
            int m = i >> 4, k = i & 15;
            int mm = m0 + m;
            float xv = 0.0f, hv = 0.0f;
            if (mm < n) {
                long long row = xoff + (long long)mm * xstr;
                xv = xbase[row * H + kc + k];
                if (!first) hv = h_in[(long long)mm * H + kc + k];
            }
            As[m][k] = xv;
            Hs[m][k] = hv;
        }
        // --- stage weight tiles (4 gates x 64 j x 16 k) ---
#pragma unroll
        for (int i = tid; i < 4 * BJ * KC; i += 256) {
            int k = i & 15, jj = (i >> 4) & 63, g = i >> 10;
            long long row = (long long)(g * H + jb + jj);
            Wi[g][jj][k] = Wih[row * H + kc + k];
            Wh[g][jj][k] = first ? 0.0f : Whh[row * H + kc + k];
        }
        __syncthreads();

        if (first) {
#pragma unroll
            for (int k = 0; k < KC; k++) {
                unsigned long long a2[8];
#pragma unroll
                for (int r = 0; r < 8; r++) {
                    float a = As[ty * 8 + r][k];
                    a2[r] = pack2(a, a);
                }
                unsigned long long wip[4];
#pragma unroll
                for (int g = 0; g < 4; g++)
                    wip[g] = pack2(Wi[g][tx][k], Wi[g][tx + 32][k]);
#pragma unroll
                for (int r = 0; r < 8; r++)
#pragma unroll
                    for (int g = 0; g < 4; g++)
                        FFMA2(acc[r][g], a2[r], wip[g]);
            }
        } else {
#pragma unroll
            for (int k = 0; k < KC; k++) {
                unsigned long long a2[8], h2[8];
#pragma unroll
                for (int r = 0; r < 8; r++) {
                    float a = As[ty * 8 + r][k];
                    float hh = Hs[ty * 8 + r][k];
                    a2[r] = pack2(a, a);
                    h2[r] = pack2(hh, hh);
                }
                unsigned long long wip[4], whp[4];
#pragma unroll
                for (int g = 0; g < 4; g++) {
                    wip[g] = pack2(Wi[g][tx][k], Wi[g][tx + 32][k]);
                    whp[g] = pack2(Wh[g][tx][k], Wh[g][tx + 32][k]);
                }
#pragma unroll
                for (int r = 0; r < 8; r++)
#pragma unroll
                    for (int g = 0; g < 4; g++) {
                        FFMA2(acc[r][g], a2[r], wip[g]);
                        FFMA2(acc[r][g], h2[r], whp[g]);
                    }
            }
        }
        __syncthreads();
    }

    // --- epilogue: gate nonlinearities + state update ---
#pragma unroll
    for (int r = 0; r < 8; r++) {
        int mm = m0 + ty * 8 + r;
        if (mm >= n) continue;
        float av[2][4];
#pragma unroll
        for (int g = 0; g < 4; g++) unpack2(acc[r][g], av[0][g], av[1][g]);
#pragma unroll
        for (int u = 0; u < 2; u++) {
            int j = jb + tx + u * 32;
            float gi = av[u][0] + bih[j]         + bhh[j];
            float gf = av[u][1] + bih[H + j]     + bhh[H + j];
            float gg = av[u][2] + bih[2 * H + j] + bhh[2 * H + j];
            float go = av[u][3] + bih[3 * H + j] + bhh[3 * H + j];
            float cprev = first ? 0.0f : c_in[(long long)mm * H + j];
            float c = sigm(gf) * cprev + sigm(gi) * tanhf(gg);
            float h = sigm(go) * tanhf(c);
            h_out[(long long)mm * H + j] = h;
            if (!last) c_out[(long long)mm * H + j] = c;
        }
    }
}

// enc = tanh([el, er] @ Wenc^T + benc), written to g_enc rows [off, off+n)
__global__ __launch_bounds__(256)
void enc_kernel(const float* __restrict__ Wenc, const float* __restrict__ benc,
                int n, long long off, float* __restrict__ outp)
{
    __shared__ float As[BM][KC + 1];
    __shared__ float Ws[BJ][KC + 1];

    const int tid = threadIdx.x;
    const int ty = tid >> 5, tx = tid & 31;
    const int m0 = blockIdx.x * BM;
    const int jb = blockIdx.y * BJ;

    unsigned long long acc[8];
#pragma unroll
    for (int r = 0; r < 8; r++) acc[r] = 0ull;

    for (int seg = 0; seg < 2; seg++) {
        const float* E = seg ? g_er : g_el;
        for (int kc = 0; kc < H; kc += KC) {
#pragma unroll
            for (int i = tid; i < BM * KC; i += 256) {
                int m = i >> 4, k = i & 15;
                int mm = m0 + m;
                As[m][k] = (mm < n) ? E[(long long)mm * H + kc + k] : 0.0f;
            }
#pragma unroll
            for (int i = tid; i < BJ * KC; i += 256) {
                int k = i & 15, jj = i >> 4;
                Ws[jj][k] = Wenc[(long long)(jb + jj) * (2 * H) + seg * H + kc + k];
            }
            __syncthreads();
#pragma unroll
            for (int k = 0; k < KC; k++) {
                unsigned long long w2 = pack2(Ws[tx][k], Ws[tx + 32][k]);
#pragma unroll
                for (int r = 0; r < 8; r++) {
                    float a = As[ty * 8 + r][k];
                    unsigned long long a2 = pack2(a, a);
                    FFMA2(acc[r], a2, w2);
                }
            }
            __syncthreads();
        }
    }

#pragma unroll
    for (int r = 0; r < 8; r++) {
        int mm = m0 + ty * 8 + r;
        if (mm >= n) continue;
        float a0, a1;
        unpack2(acc[r], a0, a1);
#pragma unroll
        for (int u = 0; u < 2; u++) {
            int j = jb + tx + u * 32;
            float v = tanhf((u ? a1 : a0) + benc[j]);
            g_enc[(off + mm) * H + j] = v;
            if (outp != nullptr && mm == 0) outp[j] = v;
        }
    }
}

extern "C" void kernel_launch(void* const* d_in, const int* in_sizes, int n_in,
                              void* d_out, int out_size)
{
    const float* node_init = (const float*)d_in[0];
    const float* Wih_l = (const float*)d_in[1];
    const float* Whh_l = (const float*)d_in[2];
    const float* bih_l = (const float*)d_in[3];
    const float* bhh_l = (const float*)d_in[4];
    const float* Wih_r = (const float*)d_in[5];
    const float* Whh_r = (const float*)d_in[6];
    const float* bih_r = (const float*)d_in[7];
    const float* bhh_r = (const float*)d_in[8];
    const float* Wenc  = (const float*)d_in[9];
    const float* benc  = (const float*)d_in[10];
    float* out = (float*)d_out;

    static const int       SZ[7]  = {1, 8, 64, 512, 4096, 32768, 262144};
    static const long long OFF[7] = {0, 1, 9, 73, 585, 4681, 37449};

    // ---- leaf level d=6: T=1 LSTM (h0=c0=0), x = own rows of node_init ----
    {
        int n = SZ[6]; long long off = OFF[6];
        dim3 g((n + BM - 1) / BM, 4, 2);
        lstm_step_kernel<<<g, 256>>>(node_init,
            Wih_l, Whh_l, bih_l, bhh_l, Wih_r, Whh_r, bih_r, bhh_r,
            n, /*first=*/1, /*last=*/1, /*pp=*/0,
            /*xl*/ 0, off, 1, /*xr*/ 0, off, 1);
        dim3 ge((n + BM - 1) / BM, 4, 1);
        enc_kernel<<<ge, 256>>>(Wenc, benc, n, off, nullptr);
    }

    // ---- levels d=5..0: T=5 chains ----
    for (int d = 5; d >= 0; d--) {
        int n = SZ[d];
        long long off = OFF[d], coff = OFF[d + 1];
        dim3 g((n + BM - 1) / BM, 4, 2);
        dim3 ge((n + BM - 1) / BM, 4, 1);
        for (int t = 0; t < 5; t++) {
            int first = (t == 0), last = (t == 4), pp = (t & 1) ^ 1;
            // left chain:  t=0..3 -> child (3-t), t=4 -> own
            int xsl, xstr_l; long long xol;
            if (t < 4) { xsl = 1; xol = coff + (3 - t); xstr_l = 8; }
            else       { xsl = 0; xol = off;            xstr_l = 1; }
            // right chain: t=0 -> own, t=1..4 -> child (3+t)
            int xsr, xstr_r; long long xorr;
            if (t == 0) { xsr = 0; xorr = off;            xstr_r = 1; }
            else        { xsr = 1; xorr = coff + (3 + t); xstr_r = 8; }
            lstm_step_kernel<<<g, 256>>>(node_init,
                Wih_l, Whh_l, bih_l, bhh_l, Wih_r, Whh_r, bih_r, bhh_r,
                n, first, last, pp, xsl, xol, xstr_l, xsr, xorr, xstr_r);
        }
        enc_kernel<<<ge, 256>>>(Wenc, benc, n, off, (d == 0) ? out : nullptr);
    }
}

// round 15
// speedup vs baseline: 1.2641x; 1.2641x over previous
#include <cuda_runtime.h>
#include <math.h>

#define H 256

#define BM 64
#define BJ 64
#define KC 16
#define WPAD 66   // row pad for W tiles (conflict-free writes, 8B-aligned reads)

#define HMAX_ROWS 32768
#define LEAF_N    262144
#define N_TOTAL   299593

// Scratch (device globals -- no allocation allowed)
__device__ float g_enc[(size_t)N_TOTAL * H];          // encoder outputs per tree node
__device__ float g_el [(size_t)LEAF_N  * H];          // left-LSTM final hidden
__device__ float g_er [(size_t)LEAF_N  * H];          // right-LSTM final hidden
__device__ float g_h[2][2][(size_t)HMAX_ROWS * H];    // [side][ping] hidden state
__device__ float g_c[2][2][(size_t)HMAX_ROWS * H];    // [side][ping] cell state

__device__ __forceinline__ float sigm(float x) { return 1.0f / (1.0f + expf(-x)); }

// ---- packed fp32x2 helpers (sm_103a FFMA2 path, PTX-only) ----
__device__ __forceinline__ unsigned long long pack2(float lo, float hi) {
    unsigned long long r;
    asm("mov.b64 %0, {%1, %2};" : "=l"(r)
        : "r"(__float_as_uint(lo)), "r"(__float_as_uint(hi)));
    return r;
}
__device__ __forceinline__ void unpack2(unsigned long long v, float& lo, float& hi) {
    unsigned int a, b;
    asm("mov.b64 {%0, %1}, %2;" : "=r"(a), "=r"(b) : "l"(v));
    lo = __uint_as_float(a);
    hi = __uint_as_float(b);
}
#define FFMA2(acc, a, b) \
    asm("fma.rn.f32x2 %0, %1, %2, %0;" : "+l"(acc) : "l"(a), "l"(b))

// One LSTM step for both the left (z=0) and right (z=1) chains.
// gates[n,1024] = X[n,256] @ Wih^T (+ Hprev[n,256] @ Whh^T) + bih + bhh
// X rows come from node_init (xsrc=0) or g_enc (xsrc=1) at row = xoff + m*xstr.
// Lane pairing: thread tx covers j = jb + 2*tx and jb + 2*tx + 1 (packed fp32x2).
__global__ __launch_bounds__(256, 2)
void lstm_step_kernel(
    const float* __restrict__ node_init,
    const float* __restrict__ Wih_l, const float* __restrict__ Whh_l,
    const float* __restrict__ bih_l, const float* __restrict__ bhh_l,
    const float* __restrict__ Wih_r, const float* __restrict__ Whh_r,
    const float* __restrict__ bih_r, const float* __restrict__ bhh_r,
    int n, int first, int last, int pp,
    int xsrc_l, long long xoff_l, int xstr_l,
    int xsrc_r, long long xoff_r, int xstr_r)
{
    const int side = blockIdx.z;
    const float* Wih = side ? Wih_r : Wih_l;
    const float* Whh = side ? Whh_r : Whh_l;
    const float* bih = side ? bih_r : bih_l;
    const float* bhh = side ? bhh_r : bhh_l;
    const int       xsrc = side ? xsrc_r : xsrc_l;
    const long long xoff = side ? xoff_r : xoff_l;
    const int       xstr = side ? xstr_r : xstr_l;

    const float* xbase = xsrc ? g_enc : node_init;
    const float* h_in  = g_h[side][pp];
    const float* c_in  = g_c[side][pp];
    float* h_out = last ? (side ? g_er : g_el) : g_h[side][pp ^ 1];
    float* c_out = g_c[side][pp ^ 1];

    __shared__ float As[BM][KC + 2];
    __shared__ float Hs[BM][KC + 2];
    __shared__ float Wi[4][KC][WPAD];   // j-fastest: Wi[g][k][jj]
    __shared__ float Wh[4][KC][WPAD];

    const int tid = threadIdx.x;
    const int ty = tid >> 5, tx = tid & 31;
    const int m0 = blockIdx.x * BM;
    const int jb = blockIdx.y * BJ;

    // packed accumulators: lane pair (j = jb+2tx, j = jb+2tx+1)
    unsigned long long acc[8][4];
#pragma unroll
    for (int r = 0; r < 8; r++)
#pragma unroll
        for (int g = 0; g < 4; g++) acc[r][g] = 0ull;

    for (int kc = 0; kc < H; kc += KC) {
        // --- stage A/H tiles (broadcast-read layout [m][k]) ---
#pragma unroll
        for (int i = tid; i < BM * KC; i += 256) {
            int m = i >> 4, k = i & 15;
            int mm = m0 + m;
            float xv = 0.0f, hv = 0.0f;
            if (mm < n) {
                long long row = xoff + (long long)mm * xstr;
                xv = xbase[row * H + kc + k];
                if (!first) hv = h_in[(long long)mm * H + kc + k];
            }
            As[m][k] = xv;
            Hs[m][k] = hv;
        }
        // --- stage weight tiles, j-fastest so lane pairs are contiguous ---
#pragma unroll
        for (int i = tid; i < 4 * BJ * KC; i += 256) {
            int k = i & 15, jj = (i >> 4) & 63, g = i >> 10;
            long long row = (long long)(g * H + jb + jj);
            Wi[g][k][jj] = Wih[row * H + kc + k];
            Wh[g][k][jj] = first ? 0.0f : Whh[row * H + kc + k];
        }
        __syncthreads();

        if (first) {
#pragma unroll
            for (int k = 0; k < KC; k++) {
                unsigned long long wip[4];
#pragma unroll
                for (int g = 0; g < 4; g++)
                    wip[g] = *(const unsigned long long*)&Wi[g][k][tx * 2];
#pragma unroll
                for (int r = 0; r < 8; r++) {
                    float a = As[ty * 8 + r][k];
                    unsigned long long a2 = pack2(a, a);
#pragma unroll
                    for (int g = 0; g < 4; g++)
                        FFMA2(acc[r][g], a2, wip[g]);
                }
            }
        } else {
#pragma unroll
            for (int k = 0; k < KC; k++) {
                unsigned long long wip[4], whp[4];
#pragma unroll
                for (int g = 0; g < 4; g++) {
                    wip[g] = *(const unsigned long long*)&Wi[g][k][tx * 2];
                    whp[g] = *(const unsigned long long*)&Wh[g][k][tx * 2];
                }
#pragma unroll
                for (int r = 0; r < 8; r++) {
                    float a = As[ty * 8 + r][k];
                    float hh = Hs[ty * 8 + r][k];
                    unsigned long long a2 = pack2(a, a);
                    unsigned long long h2 = pack2(hh, hh);
#pragma unroll
                    for (int g = 0; g < 4; g++) {
                        FFMA2(acc[r][g], a2, wip[g]);
                        FFMA2(acc[r][g], h2, whp[g]);
                    }
                }
            }
        }
        __syncthreads();
    }

    // --- epilogue: gate nonlinearities + state update (float2 over j-pair) ---
    const int j0 = jb + tx * 2;
    const float2 bi0 = *(const float2*)&bih[j0];
    const float2 bh0 = *(const float2*)&bhh[j0];
    const float2 bi1 = *(const float2*)&bih[H + j0];
    const float2 bh1 = *(const float2*)&bhh[H + j0];
    const float2 bi2 = *(const float2*)&bih[2 * H + j0];
    const float2 bh2 = *(const float2*)&bhh[2 * H + j0];
    const float2 bi3 = *(const float2*)&bih[3 * H + j0];
    const float2 bh3 = *(const float2*)&bhh[3 * H + j0];

#pragma unroll
    for (int r = 0; r < 8; r++) {
        int mm = m0 + ty * 8 + r;
        if (mm >= n) continue;
        float av[4][2];
#pragma unroll
        for (int g = 0; g < 4; g++) unpack2(acc[r][g], av[g][0], av[g][1]);

        float2 cprev = make_float2(0.0f, 0.0f);
        if (!first) cprev = *(const float2*)&c_in[(long long)mm * H + j0];

        float2 hv, cv;
        {
            float gi = av[0][0] + bi0.x + bh0.x;
            float gf = av[1][0] + bi1.x + bh1.x;
            float gg = av[2][0] + bi2.x + bh2.x;
            float go = av[3][0] + bi3.x + bh3.x;
            float c = sigm(gf) * cprev.x + sigm(gi) * tanhf(gg);
            cv.x = c;
            hv.x = sigm(go) * tanhf(c);
        }
        {
            float gi = av[0][1] + bi0.y + bh0.y;
            float gf = av[1][1] + bi1.y + bh1.y;
            float gg = av[2][1] + bi2.y + bh2.y;
            float go = av[3][1] + bi3.y + bh3.y;
            float c = sigm(gf) * cprev.y + sigm(gi) * tanhf(gg);
            cv.y = c;
            hv.y = sigm(go) * tanhf(c);
        }
        *(float2*)&h_out[(long long)mm * H + j0] = hv;
        if (!last) *(float2*)&c_out[(long long)mm * H + j0] = cv;
    }
}

// enc = tanh([el, er] @ Wenc^T + benc), written to g_enc rows [off, off+n)
__global__ __launch_bounds__(256)
void enc_kernel(const float* __restrict__ Wenc, const float* __restrict__ benc,
                int n, long long off, float* __restrict__ outp)
{
    __shared__ float As[BM][KC + 1];
    __shared__ float Ws[BJ][KC + 1];

    const int tid = threadIdx.x;
    const int ty = tid >> 5, tx = tid & 31;
    const int m0 = blockIdx.x * BM;
    const int jb = blockIdx.y * BJ;

    unsigned long long acc[8];
#pragma unroll
    for (int r = 0; r < 8; r++) acc[r] = 0ull;

    for (int seg = 0; seg < 2; seg++) {
        const float* E = seg ? g_er : g_el;
        for (int kc = 0; kc < H; kc += KC) {
#pragma unroll
            for (int i = tid; i < BM * KC; i += 256) {
                int m = i >> 4, k = i & 15;
                int mm = m0 + m;
                As[m][k] = (mm < n) ? E[(long long)mm * H + kc + k] : 0.0f;
            }
#pragma unroll
            for (int i = tid; i < BJ * KC; i += 256) {
                int k = i & 15, jj = i >> 4;
                Ws[jj][k] = Wenc[(long long)(jb + jj) * (2 * H) + seg * H + kc + k];
            }
            __syncthreads();
#pragma unroll
            for (int k = 0; k < KC; k++) {
                unsigned long long w2 = pack2(Ws[tx][k], Ws[tx + 32][k]);
#pragma unroll
                for (int r = 0; r < 8; r++) {
                    float a = As[ty * 8 + r][k];
                    unsigned long long a2 = pack2(a, a);
                    FFMA2(acc[r], a2, w2);
                }
            }
            __syncthreads();
        }
    }

#pragma unroll
    for (int r = 0; r < 8; r++) {
        int mm = m0 + ty * 8 + r;
        if (mm >= n) continue;
        float a0, a1;
        unpack2(acc[r], a0, a1);
#pragma unroll
        for (int u = 0; u < 2; u++) {
            int j = jb + tx + u * 32;
            float v = tanhf((u ? a1 : a0) + benc[j]);
            g_enc[(off + mm) * H + j] = v;
            if (outp != nullptr && mm == 0) outp[j] = v;
        }
    }
}

extern "C" void kernel_launch(void* const* d_in, const int* in_sizes, int n_in,
                              void* d_out, int out_size)
{
    const float* node_init = (const float*)d_in[0];
    const float* Wih_l = (const float*)d_in[1];
    const float* Whh_l = (const float*)d_in[2];
    const float* bih_l = (const float*)d_in[3];
    const float* bhh_l = (const float*)d_in[4];
    const float* Wih_r = (const float*)d_in[5];
    const float* Whh_r = (const float*)d_in[6];
    const float* bih_r = (const float*)d_in[7];
    const float* bhh_r = (const float*)d_in[8];
    const float* Wenc  = (const float*)d_in[9];
    const float* benc  = (const float*)d_in[10];
    float* out = (float*)d_out;

    static const int       SZ[7]  = {1, 8, 64, 512, 4096, 32768, 262144};
    static const long long OFF[7] = {0, 1, 9, 73, 585, 4681, 37449};

    // ---- leaf level d=6: T=1 LSTM (h0=c0=0), x = own rows of node_init ----
    {
        int n = SZ[6]; long long off = OFF[6];
        dim3 g((n + BM - 1) / BM, 4, 2);
        lstm_step_kernel<<<g, 256>>>(node_init,
            Wih_l, Whh_l, bih_l, bhh_l, Wih_r, Whh_r, bih_r, bhh_r,
            n, /*first=*/1, /*last=*/1, /*pp=*/0,
            /*xl*/ 0, off, 1, /*xr*/ 0, off, 1);
        dim3 ge((n + BM - 1) / BM, 4, 1);
        enc_kernel<<<ge, 256>>>(Wenc, benc, n, off, nullptr);
    }

    // ---- levels d=5..0: T=5 chains ----
    for (int d = 5; d >= 0; d--) {
        int n = SZ[d];
        long long off = OFF[d], coff = OFF[d + 1];
        dim3 g((n + BM - 1) / BM, 4, 2);
        dim3 ge((n + BM - 1) / BM, 4, 1);
        for (int t = 0; t < 5; t++) {
            int first = (t == 0), last = (t == 4), pp = (t & 1) ^ 1;
            // left chain:  t=0..3 -> child (3-t), t=4 -> own
            int xsl, xstr_l; long long xol;
            if (t < 4) { xsl = 1; xol = coff + (3 - t); xstr_l = 8; }
            else       { xsl = 0; xol = off;            xstr_l = 1; }
            // right chain: t=0 -> own, t=1..4 -> child (3+t)
            int xsr, xstr_r; long long xorr;
            if (t == 0) { xsr = 0; xorr = off;            xstr_r = 1; }
            else        { xsr = 1; xorr = coff + (3 + t); xstr_r = 8; }
            lstm_step_kernel<<<g, 256>>>(node_init,
                Wih_l, Whh_l, bih_l, bhh_l, Wih_r, Whh_r, bih_r, bhh_r,
                n, first, last, pp, xsl, xol, xstr_l, xsr, xorr, xstr_r);
        }
        enc_kernel<<<ge, 256>>>(Wenc, benc, n, off, (d == 0) ? out : nullptr);
    }
}

// round 16
// speedup vs baseline: 1.5519x; 1.2277x over previous
#include <cuda_runtime.h>
#include <cuda_bf16.h>
#include <math.h>

#define H 256
#define BMM 128          // rows per block
#define NT 512           // threads per block
#define KB 32            // k-chunk
#define APAD 40          // A tile row pitch (bf16): 80B = 5*16B, conflict-free ldmatrix
#define WCOLS 256        // W tile cols per block (64 j * 4 gates interleaved)
#define WPITCH 264       // W tile row pitch (bf16): 528B = 33*16B, conflict-free

#define HMAX_ROWS 32768
#define LEAF_N    262144
#define N_TOTAL   299593

// ---- fp32 state scratch (device globals) ----
__device__ float g_enc[(size_t)N_TOTAL * H];
__device__ float g_el [(size_t)LEAF_N  * H];
__device__ float g_er [(size_t)LEAF_N  * H];
__device__ float g_h[2][2][(size_t)HMAX_ROWS * H];
__device__ float g_c[2][2][(size_t)HMAX_ROWS * H];

// ---- preconverted weights: k-major, gate-interleaved cols (col = j*4+g), hi/lo bf16 ----
__device__ __nv_bfloat16 g_Wk_hi[2][512][1024];
__device__ __nv_bfloat16 g_Wk_lo[2][512][1024];
__device__ __nv_bfloat16 g_We_hi[512][256];     // Wenc k-major: [k][j]
__device__ __nv_bfloat16 g_We_lo[512][256];
__device__ float g_bsum[2][1024];               // bih+bhh, layout g*256+j

__device__ __forceinline__ float sigm(float x) { return 1.0f / (1.0f + expf(-x)); }

// ---- mma.sync helpers ----
__device__ __forceinline__ void ldsm4(unsigned& r0, unsigned& r1, unsigned& r2, unsigned& r3, unsigned addr) {
    asm volatile("ldmatrix.sync.aligned.m8n8.x4.shared.b16 {%0,%1,%2,%3}, [%4];"
                 : "=r"(r0), "=r"(r1), "=r"(r2), "=r"(r3) : "r"(addr));
}
__device__ __forceinline__ void ldsm4t(unsigned& r0, unsigned& r1, unsigned& r2, unsigned& r3, unsigned addr) {
    asm volatile("ldmatrix.sync.aligned.m8n8.x4.trans.shared.b16 {%0,%1,%2,%3}, [%4];"
                 : "=r"(r0), "=r"(r1), "=r"(r2), "=r"(r3) : "r"(addr));
}
__device__ __forceinline__ void mma16816(float* c, const unsigned* a, unsigned b0, unsigned b1) {
    asm volatile("mma.sync.aligned.m16n8k16.row.col.f32.bf16.bf16.f32 "
                 "{%0,%1,%2,%3}, {%4,%5,%6,%7}, {%8,%9}, {%0,%1,%2,%3};"
                 : "+f"(c[0]), "+f"(c[1]), "+f"(c[2]), "+f"(c[3])
                 : "r"(a[0]), "r"(a[1]), "r"(a[2]), "r"(a[3]), "r"(b0), "r"(b1));
}

// smem layout (dynamic): As_hi | As_lo | Wk_hi | Wk_lo
#define SM_AS_HI 0
#define SM_AS_LO (BMM * APAD * 2)
#define SM_WK_HI (2 * BMM * APAD * 2)
#define SM_WK_LO (2 * BMM * APAD * 2 + KB * WPITCH * 2)
#define SMEM_BYTES (2 * BMM * APAD * 2 + 2 * KB * WPITCH * 2)   // 20480 + 33792 = 54272

// ---- prep: convert weights to hi/lo bf16 layouts + bias sums ----
__global__ void prep_kernel(
    const float* __restrict__ Wih_l, const float* __restrict__ Whh_l,
    const float* __restrict__ bih_l, const float* __restrict__ bhh_l,
    const float* __restrict__ Wih_r, const float* __restrict__ Whh_r,
    const float* __restrict__ bih_r, const float* __restrict__ bhh_r,
    const float* __restrict__ Wenc)
{
    const int T1 = 2 * 512 * 1024;
    const int T2 = 512 * 256;
    int idx = blockIdx.x * blockDim.x + threadIdx.x;
    if (idx < T1) {
        int s = idx >> 19;              // /(512*1024)
        int rem = idx & ((512 * 1024) - 1);
        int k = rem >> 10;
        int col = rem & 1023;
        int g = col & 3, j = col >> 2;
        const float* Wi = s ? Wih_r : Wih_l;
        const float* Wh = s ? Whh_r : Whh_l;
        float v = (k < 256) ? Wi[(g * 256 + j) * 256 + k]
                            : Wh[(g * 256 + j) * 256 + (k - 256)];
        __nv_bfloat16 hi = __float2bfloat16(v);
        __nv_bfloat16 lo = __float2bfloat16(v - __bfloat162float(hi));
        g_Wk_hi[s][k][col] = hi;
        g_Wk_lo[s][k][col] = lo;
    } else if (idx < T1 + T2) {
        int r = idx - T1;
        int k = r >> 8, j = r & 255;
        float v = Wenc[j * 512 + k];
        __nv_bfloat16 hi = __float2bfloat16(v);
        g_We_hi[k][j] = hi;
        g_We_lo[k][j] = __float2bfloat16(v - __bfloat162float(hi));
    } else if (idx < T1 + T2 + 2048) {
        int r = idx - T1 - T2;
        int s = r >> 10, i = r & 1023;
        g_bsum[s][i] = (s ? bih_r[i] + bhh_r[i] : bih_l[i] + bhh_l[i]);
    }
}

// ---- LSTM step: gates = [X|Hprev] @ Wcat^T via bf16-split mma.sync ----
__global__ __launch_bounds__(NT, 1)
void lstm_step_kernel(
    const float* __restrict__ node_init,
    int n, int first, int last, int pp, int Ktot,
    int xsrc_l, long long xoff_l, int xstr_l,
    int xsrc_r, long long xoff_r, int xstr_r)
{
    extern __shared__ char smem[];
    __nv_bfloat16* As_hi = (__nv_bfloat16*)(smem + SM_AS_HI);
    __nv_bfloat16* As_lo = (__nv_bfloat16*)(smem + SM_AS_LO);
    __nv_bfloat16* Wk_hi = (__nv_bfloat16*)(smem + SM_WK_HI);
    __nv_bfloat16* Wk_lo = (__nv_bfloat16*)(smem + SM_WK_LO);

    const int side = blockIdx.z;
    const int       xsrc = side ? xsrc_r : xsrc_l;
    const long long xoff = side ? xoff_r : xoff_l;
    const int       xstr = side ? xstr_r : xstr_l;

    const float* xbase = xsrc ? g_enc : node_init;
    const float* h_in  = g_h[side][pp];
    const float* c_in  = g_c[side][pp];
    float* h_out = last ? (side ? g_er : g_el) : g_h[side][pp ^ 1];
    float* c_out = g_c[side][pp ^ 1];

    const unsigned* Wh32 = (const unsigned*)&g_Wk_hi[side][0][0];
    const unsigned* Wl32 = (const unsigned*)&g_Wk_lo[side][0][0];

    const int tid = threadIdx.x;
    const int lane = tid & 31;
    const int wid = tid >> 5;
    const int wm = wid >> 2, wn = wid & 3;
    const int m0 = blockIdx.x * BMM;
    const int jb = blockIdx.y * 64;

    float acc[2][8][4];
#pragma unroll
    for (int a = 0; a < 2; a++)
#pragma unroll
        for (int f = 0; f < 8; f++)
#pragma unroll
            for (int c = 0; c < 4; c++) acc[a][f][c] = 0.0f;

    const unsigned as_hi_base = (unsigned)__cvta_generic_to_shared(As_hi);
    const unsigned as_lo_base = (unsigned)__cvta_generic_to_shared(As_lo);
    const unsigned wk_hi_base = (unsigned)__cvta_generic_to_shared(Wk_hi);
    const unsigned wk_lo_base = (unsigned)__cvta_generic_to_shared(Wk_lo);

    for (int kc = 0; kc < Ktot; kc += KB) {
        // --- stage A tile (fp32 -> hi/lo bf16) ---
#pragma unroll
        for (int i = tid; i < BMM * KB; i += NT) {
            int m = i >> 5, kk = i & 31;
            int mm = m0 + m;
            float v = 0.0f;
            if (mm < n) {
                int kg = kc + kk;
                if (kg < 256) {
                    long long row = xoff + (long long)mm * xstr;
                    v = xbase[row * H + kg];
                } else {
                    v = h_in[(long long)mm * H + (kg - 256)];
                }
            }
            __nv_bfloat16 hi = __float2bfloat16(v);
            As_hi[m * APAD + kk] = hi;
            As_lo[m * APAD + kk] = __float2bfloat16(v - __bfloat162float(hi));
        }
        // --- stage W tile (bf16x2 loads, k-major, cols jb*4..jb*4+255) ---
#pragma unroll
        for (int i = tid; i < (KB * WCOLS) / 2; i += NT) {
            int kk = i >> 7, cc = i & 127;
            size_t gidx = (size_t)(kc + kk) * 512 + jb * 2 + cc;
            *(unsigned*)&Wk_hi[kk * WPITCH + cc * 2] = Wh32[gidx];
            *(unsigned*)&Wk_lo[kk * WPITCH + cc * 2] = Wl32[gidx];
        }
        __syncthreads();

#pragma unroll
        for (int ks = 0; ks < 2; ks++) {
            const int krow = ks * 16;
            unsigned ah[2][4], al[2][4];
#pragma unroll
            for (int mf = 0; mf < 2; mf++) {
                unsigned off = ((wm * 32 + mf * 16 + (lane & 15)) * APAD
                                + krow + ((lane >> 4) << 3)) * 2;
                ldsm4(ah[mf][0], ah[mf][1], ah[mf][2], ah[mf][3], as_hi_base + off);
                ldsm4(al[mf][0], al[mf][1], al[mf][2], al[mf][3], as_lo_base + off);
            }
#pragma unroll
            for (int q = 0; q < 4; q++) {
                unsigned boff = ((krow + (lane & 15)) * WPITCH
                                 + wn * 64 + q * 16 + ((lane >> 4) << 3)) * 2;
                unsigned bh[4], bl[4];
                ldsm4t(bh[0], bh[1], bh[2], bh[3], wk_hi_base + boff);
                ldsm4t(bl[0], bl[1], bl[2], bl[3], wk_lo_base + boff);
#pragma unroll
                for (int mf = 0; mf < 2; mf++)
#pragma unroll
                    for (int sub = 0; sub < 2; sub++) {
                        int f = q * 2 + sub;
                        mma16816(acc[mf][f], ah[mf], bh[sub * 2], bh[sub * 2 + 1]);
                        mma16816(acc[mf][f], ah[mf], bl[sub * 2], bl[sub * 2 + 1]);
                        mma16816(acc[mf][f], al[mf], bh[sub * 2], bh[sub * 2 + 1]);
                    }
            }
        }
        __syncthreads();
    }

    // --- epilogue: shfl gate exchange + LSTM cell ---
    const float* bs = &g_bsum[side][0];
#pragma unroll
    for (int mf = 0; mf < 2; mf++)
#pragma unroll
        for (int rh = 0; rh < 2; rh++) {
            int m = m0 + wm * 32 + mf * 16 + rh * 8 + (lane >> 2);
#pragma unroll
            for (int f = 0; f < 8; f++) {
                float ve = acc[mf][f][rh * 2 + 0];
                float vo = acc[mf][f][rh * 2 + 1];
                float pe = __shfl_xor_sync(0xffffffffu, ve, 1);
                float po = __shfl_xor_sync(0xffffffffu, vo, 1);
                if (((lane & 1) == 0) && m < n) {
                    int j = jb + (wn << 4) + f * 2 + ((lane & 3) >> 1);
                    float gi = ve + bs[j];
                    float gf = vo + bs[256 + j];
                    float gg = pe + bs[512 + j];
                    float go = po + bs[768 + j];
                    float cprev = first ? 0.0f : c_in[(long long)m * H + j];
                    float c = sigm(gf) * cprev + sigm(gi) * tanhf(gg);
                    float h = sigm(go) * tanhf(c);
                    h_out[(long long)m * H + j] = h;
                    if (!last) c_out[(long long)m * H + j] = c;
                }
            }
        }
}

// ---- encoder: enc = tanh([el|er] @ Wenc^T + benc) ----
__global__ __launch_bounds__(NT, 1)
void enc_kernel(const float* __restrict__ benc, int n, long long off,
                float* __restrict__ outp)
{
    extern __shared__ char smem[];
    __nv_bfloat16* As_hi = (__nv_bfloat16*)(smem + SM_AS_HI);
    __nv_bfloat16* As_lo = (__nv_bfloat16*)(smem + SM_AS_LO);
    __nv_bfloat16* Wk_hi = (__nv_bfloat16*)(smem + SM_WK_HI);
    __nv_bfloat16* Wk_lo = (__nv_bfloat16*)(smem + SM_WK_LO);

    const unsigned* Wh32 = (const unsigned*)&g_We_hi[0][0];
    const unsigned* Wl32 = (const unsigned*)&g_We_lo[0][0];

    const int tid = threadIdx.x;
    const int lane = tid & 31;
    const int wid = tid >> 5;
    const int wm = wid >> 2, wn = wid & 3;
    const int m0 = blockIdx.x * BMM;

    float acc[2][8][4];
#pragma unroll
    for (int a = 0; a < 2; a++)
#pragma unroll
        for (int f = 0; f < 8; f++)
#pragma unroll
            for (int c = 0; c < 4; c++) acc[a][f][c] = 0.0f;

    const unsigned as_hi_base = (unsigned)__cvta_generic_to_shared(As_hi);
    const unsigned as_lo_base = (unsigned)__cvta_generic_to_shared(As_lo);
    const unsigned wk_hi_base = (unsigned)__cvta_generic_to_shared(Wk_hi);
    const unsigned wk_lo_base = (unsigned)__cvta_generic_to_shared(Wk_lo);

    for (int kc = 0; kc < 512; kc += KB) {
#pragma unroll
        for (int i = tid; i < BMM * KB; i += NT) {
            int m = i >> 5, kk = i & 31;
            int mm = m0 + m;
            float v = 0.0f;
            if (mm < n) {
                int kg = kc + kk;
                v = (kg < 256) ? g_el[(long long)mm * H + kg]
                               : g_er[(long long)mm * H + (kg - 256)];
            }
            __nv_bfloat16 hi = __float2bfloat16(v);
            As_hi[m * APAD + kk] = hi;
            As_lo[m * APAD + kk] = __float2bfloat16(v - __bfloat162float(hi));
        }
#pragma unroll
        for (int i = tid; i < (KB * 256) / 2; i += NT) {
            int kk = i >> 7, cc = i & 127;
            size_t gidx = (size_t)(kc + kk) * 128 + cc;
            *(unsigned*)&Wk_hi[kk * WPITCH + cc * 2] = Wh32[gidx];
            *(unsigned*)&Wk_lo[kk * WPITCH + cc * 2] = Wl32[gidx];
        }
        __syncthreads();

#pragma unroll
        for (int ks = 0; ks < 2; ks++) {
            const int krow = ks * 16;
            unsigned ah[2][4], al[2][4];
#pragma unroll
            for (int mf = 0; mf < 2; mf++) {
                unsigned off = ((wm * 32 + mf * 16 + (lane & 15)) * APAD
                                + krow + ((lane >> 4) << 3)) * 2;
                ldsm4(ah[mf][0], ah[mf][1], ah[mf][2], ah[mf][3], as_hi_base + off);
                ldsm4(al[mf][0], al[mf][1], al[mf][2], al[mf][3], as_lo_base + off);
            }
#pragma unroll
            for (int q = 0; q < 4; q++) {
                unsigned boff = ((krow + (lane & 15)) * WPITCH
                                 + wn * 64 + q * 16 + ((lane >> 4) << 3)) * 2;
                unsigned bh[4], bl[4];
                ldsm4t(bh[0], bh[1], bh[2], bh[3], wk_hi_base + boff);
                ldsm4t(bl[0], bl[1], bl[2], bl[3], wk_lo_base + boff);
#pragma unroll
                for (int mf = 0; mf < 2; mf++)
#pragma unroll
                    for (int sub = 0; sub < 2; sub++) {
                        int f = q * 2 + sub;
                        mma16816(acc[mf][f], ah[mf], bh[sub * 2], bh[sub * 2 + 1]);
                        mma16816(acc[mf][f], ah[mf], bl[sub * 2], bl[sub * 2 + 1]);
                        mma16816(acc[mf][f], al[mf], bh[sub * 2], bh[sub * 2 + 1]);
                    }
            }
        }
        __syncthreads();
    }

#pragma unroll
    for (int mf = 0; mf < 2; mf++)
#pragma unroll
        for (int rh = 0; rh < 2; rh++) {
            int m = m0 + wm * 32 + mf * 16 + rh * 8 + (lane >> 2);
            if (m >= n) continue;
#pragma unroll
            for (int f = 0; f < 8; f++) {
                int colb = wn * 64 + f * 8 + 2 * (lane & 3);
                float v0 = tanhf(acc[mf][f][rh * 2 + 0] + benc[colb]);
                float v1 = tanhf(acc[mf][f][rh * 2 + 1] + benc[colb + 1]);
                g_enc[(off + m) * H + colb]     = v0;
                g_enc[(off + m) * H + colb + 1] = v1;
                if (outp != nullptr && m == 0) {
                    outp[colb] = v0;
                    outp[colb + 1] = v1;
                }
            }
        }
}

extern "C" void kernel_launch(void* const* d_in, const int* in_sizes, int n_in,
                              void* d_out, int out_size)
{
    const float* node_init = (const float*)d_in[0];
    const float* Wih_l = (const float*)d_in[1];
    const float* Whh_l = (const float*)d_in[2];
    const float* bih_l = (const float*)d_in[3];
    const float* bhh_l = (const float*)d_in[4];
    const float* Wih_r = (const float*)d_in[5];
    const float* Whh_r = (const float*)d_in[6];
    const float* bih_r = (const float*)d_in[7];
    const float* bhh_r = (const float*)d_in[8];
    const float* Wenc  = (const float*)d_in[9];
    const float* benc  = (const float*)d_in[10];
    float* out = (float*)d_out;

    cudaFuncSetAttribute(lstm_step_kernel, cudaFuncAttributeMaxDynamicSharedMemorySize, SMEM_BYTES);
    cudaFuncSetAttribute(enc_kernel,       cudaFuncAttributeMaxDynamicSharedMemorySize, SMEM_BYTES);

    // prep: weight conversion + bias sums
    {
        int total = 2 * 512 * 1024 + 512 * 256 + 2048;
        prep_kernel<<<(total + 255) / 256, 256>>>(
            Wih_l, Whh_l, bih_l, bhh_l, Wih_r, Whh_r, bih_r, bhh_r, Wenc);
    }

    static const int       SZ[7]  = {1, 8, 64, 512, 4096, 32768, 262144};
    static const long long OFF[7] = {0, 1, 9, 73, 585, 4681, 37449};

    // ---- leaf level d=6: T=1 LSTM (h0=c0=0, K=256) ----
    {
        int n = SZ[6]; long long off = OFF[6];
        dim3 g((n + BMM - 1) / BMM, 4, 2);
        lstm_step_kernel<<<g, NT, SMEM_BYTES>>>(node_init,
            n, /*first=*/1, /*last=*/1, /*pp=*/0, /*Ktot=*/256,
            /*xl*/ 0, off, 1, /*xr*/ 0, off, 1);
        dim3 ge((n + BMM - 1) / BMM, 1, 1);
        enc_kernel<<<ge, NT, SMEM_BYTES>>>(benc, n, off, nullptr);
    }

    // ---- levels d=5..0: T=5 chains ----
    for (int d = 5; d >= 0; d--) {
        int n = SZ[d];
        long long off = OFF[d], coff = OFF[d + 1];
        dim3 g((n + BMM - 1) / BMM, 4, 2);
        dim3 ge((n + BMM - 1) / BMM, 1, 1);
        for (int t = 0; t < 5; t++) {
            int first = (t == 0), last = (t == 4), pp = (t & 1) ^ 1;
            int Ktot = first ? 256 : 512;
            // left chain:  t=0..3 -> child (3-t), t=4 -> own
            int xsl, xstr_l; long long xol;
            if (t < 4) { xsl = 1; xol = coff + (3 - t); xstr_l = 8; }
            else       { xsl = 0; xol = off;            xstr_l = 1; }
            // right chain: t=0 -> own, t=1..4 -> child (3+t)
            int xsr, xstr_r; long long xorr;
            if (t == 0) { xsr = 0; xorr = off;            xstr_r = 1; }
            else        { xsr = 1; xorr = coff + (3 + t); xstr_r = 8; }
            lstm_step_kernel<<<g, NT, SMEM_BYTES>>>(node_init,
                n, first, last, pp, Ktot, xsl, xol, xstr_l, xsr, xorr, xstr_r);
        }
        enc_kernel<<<ge, NT, SMEM_BYTES>>>(benc, n, off, (d == 0) ? out : nullptr);
    }
}

// round 17
// speedup vs baseline: 2.5369x; 1.6347x over previous
#include <cuda_runtime.h>
#include <cuda_bf16.h>
#include <math.h>

#define H 256
#define BMM 128          // rows per block
#define NT 512           // threads per block
#define KB 32            // k-chunk
#define APAD 40          // A tile row pitch (bf16 elems): 80B, conflict-free ldmatrix
#define WPITCH 264       // W tile row pitch (bf16 elems): 528B, conflict-free

#define HMAX_ROWS 32768
#define LEAF_N    262144
#define N_TOTAL   299593

// ---- per-stage smem layout (bytes) ----
#define ST_A_HI 0
#define ST_A_LO 10240            // 128*40*2
#define ST_W_HI 20480
#define ST_W_LO 37376            // 20480 + 32*264*2
#define ST_BYTES 54272
#define NSTAGE 3
#define SMEM_BYTES (ST_BYTES * NSTAGE)   // 162816

// ---- device global scratch (no allocation allowed) ----
__device__ __nv_bfloat16 g_x_hi[(size_t)N_TOTAL * H];   // node_init split
__device__ __nv_bfloat16 g_x_lo[(size_t)N_TOTAL * H];
__device__ __nv_bfloat16 g_enc_hi[(size_t)N_TOTAL * H]; // encoder outputs split
__device__ __nv_bfloat16 g_enc_lo[(size_t)N_TOTAL * H];
__device__ __nv_bfloat16 g_el_hi[(size_t)LEAF_N * H];
__device__ __nv_bfloat16 g_el_lo[(size_t)LEAF_N * H];
__device__ __nv_bfloat16 g_er_hi[(size_t)LEAF_N * H];
__device__ __nv_bfloat16 g_er_lo[(size_t)LEAF_N * H];
__device__ __nv_bfloat16 g_h_hi[2][2][(size_t)HMAX_ROWS * H];
__device__ __nv_bfloat16 g_h_lo[2][2][(size_t)HMAX_ROWS * H];
__device__ float         g_c[2][2][(size_t)HMAX_ROWS * H];

// weights: k-major, gate-interleaved cols (col = j*4+g), hi/lo bf16
__device__ __nv_bfloat16 g_Wk_hi[2][512][1024];
__device__ __nv_bfloat16 g_Wk_lo[2][512][1024];
__device__ __nv_bfloat16 g_We_hi[512][256];     // Wenc k-major [k][j]
__device__ __nv_bfloat16 g_We_lo[512][256];
__device__ float g_bsum[2][1024];               // bih+bhh, layout g*256+j

__device__ __forceinline__ float sigm(float x) { return 1.0f / (1.0f + expf(-x)); }

// ---- async copy helpers ----
__device__ __forceinline__ void cpasync16(unsigned dst, const void* src, bool valid) {
    int sz = valid ? 16 : 0;
    asm volatile("cp.async.cg.shared.global [%0], [%1], 16, %2;"
                 :: "r"(dst), "l"(src), "r"(sz));
}
#define CP_COMMIT() asm volatile("cp.async.commit_group;" ::: "memory")

// ---- mma.sync helpers ----
__device__ __forceinline__ void ldsm4(unsigned& r0, unsigned& r1, unsigned& r2, unsigned& r3, unsigned addr) {
    asm volatile("ldmatrix.sync.aligned.m8n8.x4.shared.b16 {%0,%1,%2,%3}, [%4];"
                 : "=r"(r0), "=r"(r1), "=r"(r2), "=r"(r3) : "r"(addr));
}
__device__ __forceinline__ void ldsm4t(unsigned& r0, unsigned& r1, unsigned& r2, unsigned& r3, unsigned addr) {
    asm volatile("ldmatrix.sync.aligned.m8n8.x4.trans.shared.b16 {%0,%1,%2,%3}, [%4];"
                 : "=r"(r0), "=r"(r1), "=r"(r2), "=r"(r3) : "r"(addr));
}
__device__ __forceinline__ void mma16816(float* c, const unsigned* a, unsigned b0, unsigned b1) {
    asm volatile("mma.sync.aligned.m16n8k16.row.col.f32.bf16.bf16.f32 "
                 "{%0,%1,%2,%3}, {%4,%5,%6,%7}, {%8,%9}, {%0,%1,%2,%3};"
                 : "+f"(c[0]), "+f"(c[1]), "+f"(c[2]), "+f"(c[3])
                 : "r"(a[0]), "r"(a[1]), "r"(a[2]), "r"(a[3]), "r"(b0), "r"(b1));
}

// ---- prep: split node_init + weights into hi/lo bf16, bias sums ----
__global__ void prep_kernel(
    const float* __restrict__ node_init,
    const float* __restrict__ Wih_l, const float* __restrict__ Whh_l,
    const float* __restrict__ bih_l, const float* __restrict__ bhh_l,
    const float* __restrict__ Wih_r, const float* __restrict__ Whh_r,
    const float* __restrict__ bih_r, const float* __restrict__ bhh_r,
    const float* __restrict__ Wenc)
{
    const int TX = N_TOTAL * H;          // 76,695,808
    const int T1 = 2 * 512 * 1024;
    const int T2 = 512 * 256;
    int idx = blockIdx.x * blockDim.x + threadIdx.x;
    if (idx < TX) {
        float v = node_init[idx];
        __nv_bfloat16 hi = __float2bfloat16(v);
        g_x_hi[idx] = hi;
        g_x_lo[idx] = __float2bfloat16(v - __bfloat162float(hi));
    } else if (idx < TX + T1) {
        int r = idx - TX;
        int s = r >> 19;
        int rem = r & ((512 * 1024) - 1);
        int k = rem >> 10;
        int col = rem & 1023;
        int g = col & 3, j = col >> 2;
        const float* Wi = s ? Wih_r : Wih_l;
        const float* Wh = s ? Whh_r : Whh_l;
        float v = (k < 256) ? Wi[(g * 256 + j) * 256 + k]
                            : Wh[(g * 256 + j) * 256 + (k - 256)];
        __nv_bfloat16 hi = __float2bfloat16(v);
        g_Wk_hi[s][k][col] = hi;
        g_Wk_lo[s][k][col] = __float2bfloat16(v - __bfloat162float(hi));
    } else if (idx < TX + T1 + T2) {
        int r = idx - TX - T1;
        int k = r >> 8, j = r & 255;
        float v = Wenc[j * 512 + k];
        __nv_bfloat16 hi = __float2bfloat16(v);
        g_We_hi[k][j] = hi;
        g_We_lo[k][j] = __float2bfloat16(v - __bfloat162float(hi));
    } else if (idx < TX + T1 + T2 + 2048) {
        int r = idx - TX - T1 - T2;
        int s = r >> 10, i = r & 1023;
        g_bsum[s][i] = (s ? bih_r[i] + bhh_r[i] : bih_l[i] + bhh_l[i]);
    }
}

// ---- LSTM step: gates = [X|Hprev] @ Wcat^T via 3-MMA split bf16, cp.async pipelined ----
__global__ __launch_bounds__(NT, 1)
void lstm_step_kernel(
    int n, int first, int last, int pp, int Ktot,
    int xsrc_l, long long xoff_l, int xstr_l,
    int xsrc_r, long long xoff_r, int xstr_r)
{
    extern __shared__ char smem[];
    const unsigned smem_u32 = (unsigned)__cvta_generic_to_shared(smem);

    const int side = blockIdx.z;
    const int       xsrc = side ? xsrc_r : xsrc_l;
    const long long xoff = side ? xoff_r : xoff_l;
    const int       xstr = side ? xstr_r : xstr_l;

    const __nv_bfloat16* xb_hi = xsrc ? g_enc_hi : g_x_hi;
    const __nv_bfloat16* xb_lo = xsrc ? g_enc_lo : g_x_lo;
    const __nv_bfloat16* hin_hi = g_h_hi[side][pp];
    const __nv_bfloat16* hin_lo = g_h_lo[side][pp];
    const float* c_in  = g_c[side][pp];
    __nv_bfloat16* hout_hi = last ? (side ? g_er_hi : g_el_hi) : g_h_hi[side][pp ^ 1];
    __nv_bfloat16* hout_lo = last ? (side ? g_er_lo : g_el_lo) : g_h_lo[side][pp ^ 1];
    float* c_out = g_c[side][pp ^ 1];

    const __nv_bfloat16* Wg_hi = &g_Wk_hi[side][0][0];
    const __nv_bfloat16* Wg_lo = &g_Wk_lo[side][0][0];

    const int tid = threadIdx.x;
    const int lane = tid & 31;
    const int wid = tid >> 5;
    const int wm = wid >> 2, wn = wid & 3;
    const int m0 = blockIdx.x * BMM;
    const int jb = blockIdx.y * 64;

    float acc[2][8][4];
#pragma unroll
    for (int a = 0; a < 2; a++)
#pragma unroll
        for (int f = 0; f < 8; f++)
#pragma unroll
            for (int c = 0; c < 4; c++) acc[a][f][c] = 0.0f;

    const int nch = Ktot / KB;

    // --- stage loader: 6 cp.async per thread ---
    auto stage_load = [&](int kc, int s) {
        unsigned sb = smem_u32 + s * ST_BYTES;
        {   // A tiles: 128 rows x 4 chunks
            int row = tid >> 2, c = tid & 3;
            int mm = m0 + row;
            bool valid = (mm < n);
            int kg = kc + c * 8;
            const __nv_bfloat16 *sh, *sl;
            if (kg < 256) {
                long long r = xoff + (long long)mm * xstr;
                sh = xb_hi + r * H + kg;
                sl = xb_lo + r * H + kg;
            } else {
                sh = hin_hi + (long long)mm * H + (kg - 256);
                sl = hin_lo + (long long)mm * H + (kg - 256);
            }
            unsigned d = sb + ST_A_HI + row * 80 + c * 16;
            cpasync16(d, sh, valid);
            cpasync16(d + (ST_A_LO - ST_A_HI), sl, valid);
        }
        // W tiles: 32 k-rows x 32 chunks (512B of cols)
#pragma unroll
        for (int rep = 0; rep < 2; rep++) {
            int idx = tid + rep * NT;
            int kk = idx >> 5, c = idx & 31;
            size_t goff = (size_t)(kc + kk) * 1024 + jb * 4 + c * 8;
            unsigned d = sb + ST_W_HI + kk * 528 + c * 16;
            cpasync16(d, Wg_hi + goff, true);
            cpasync16(d + (ST_W_LO - ST_W_HI), Wg_lo + goff, true);
        }
    };

    // --- pipeline prologue ---
    stage_load(0, 0); CP_COMMIT();
    if (nch > 1) { stage_load(KB, 1); CP_COMMIT(); }

    for (int ci = 0; ci < nch; ci++) {
        if (ci + 1 < nch) asm volatile("cp.async.wait_group 1;" ::: "memory");
        else              asm volatile("cp.async.wait_group 0;" ::: "memory");
        __syncthreads();
        if (ci + 2 < nch) { stage_load((ci + 2) * KB, (ci + 2) % NSTAGE); CP_COMMIT(); }

        const unsigned sb = smem_u32 + (ci % NSTAGE) * ST_BYTES;
        const unsigned as_hi_base = sb + ST_A_HI;
        const unsigned as_lo_base = sb + ST_A_LO;
        const unsigned wk_hi_base = sb + ST_W_HI;
        const unsigned wk_lo_base = sb + ST_W_LO;

#pragma unroll
        for (int ks = 0; ks < 2; ks++) {
            const int krow = ks * 16;
            unsigned ah[2][4], al[2][4];
#pragma unroll
            for (int mf = 0; mf < 2; mf++) {
                unsigned off = ((wm * 32 + mf * 16 + (lane & 15)) * APAD
                                + krow + ((lane >> 4) << 3)) * 2;
                ldsm4(ah[mf][0], ah[mf][1], ah[mf][2], ah[mf][3], as_hi_base + off);
                ldsm4(al[mf][0], al[mf][1], al[mf][2], al[mf][3], as_lo_base + off);
            }
#pragma unroll
            for (int q = 0; q < 4; q++) {
                unsigned boff = ((krow + (lane & 15)) * WPITCH
                                 + wn * 64 + q * 16 + ((lane >> 4) << 3)) * 2;
                unsigned bh[4], bl[4];
                ldsm4t(bh[0], bh[1], bh[2], bh[3], wk_hi_base + boff);
                ldsm4t(bl[0], bl[1], bl[2], bl[3], wk_lo_base + boff);
#pragma unroll
                for (int mf = 0; mf < 2; mf++)
#pragma unroll
                    for (int sub = 0; sub < 2; sub++) {
                        int f = q * 2 + sub;
                        mma16816(acc[mf][f], ah[mf], bh[sub * 2], bh[sub * 2 + 1]);
                        mma16816(acc[mf][f], ah[mf], bl[sub * 2], bl[sub * 2 + 1]);
                        mma16816(acc[mf][f], al[mf], bh[sub * 2], bh[sub * 2 + 1]);
                    }
            }
        }
    }

    // --- epilogue: shfl gate exchange + LSTM cell ---
    const float* bs = &g_bsum[side][0];
#pragma unroll
    for (int mf = 0; mf < 2; mf++)
#pragma unroll
        for (int rh = 0; rh < 2; rh++) {
            int m = m0 + wm * 32 + mf * 16 + rh * 8 + (lane >> 2);
#pragma unroll
            for (int f = 0; f < 8; f++) {
                float ve = acc[mf][f][rh * 2 + 0];
                float vo = acc[mf][f][rh * 2 + 1];
                float pe = __shfl_xor_sync(0xffffffffu, ve, 1);
                float po = __shfl_xor_sync(0xffffffffu, vo, 1);
                if (((lane & 1) == 0) && m < n) {
                    int j = jb + (wn << 4) + f * 2 + ((lane & 3) >> 1);
                    float gi = ve + bs[j];
                    float gf = vo + bs[256 + j];
                    float gg = pe + bs[512 + j];
                    float go = po + bs[768 + j];
                    size_t o = (size_t)m * H + j;
                    float cprev = first ? 0.0f : c_in[o];
                    float c = sigm(gf) * cprev + sigm(gi) * tanhf(gg);
                    float h = sigm(go) * tanhf(c);
                    __nv_bfloat16 hh = __float2bfloat16(h);
                    hout_hi[o] = hh;
                    hout_lo[o] = __float2bfloat16(h - __bfloat162float(hh));
                    if (!last) c_out[o] = c;
                }
            }
        }
}

// ---- encoder: enc = tanh([el|er] @ Wenc^T + benc) ----
__global__ __launch_bounds__(NT, 1)
void enc_kernel(const float* __restrict__ benc, int n, long long off,
                float* __restrict__ outp)
{
    extern __shared__ char smem[];
    const unsigned smem_u32 = (unsigned)__cvta_generic_to_shared(smem);

    const int tid = threadIdx.x;
    const int lane = tid & 31;
    const int wid = tid >> 5;
    const int wm = wid >> 2, wn = wid & 3;
    const int m0 = blockIdx.x * BMM;

    float acc[2][8][4];
#pragma unroll
    for (int a = 0; a < 2; a++)
#pragma unroll
        for (int f = 0; f < 8; f++)
#pragma unroll
            for (int c = 0; c < 4; c++) acc[a][f][c] = 0.0f;

    const int nch = 512 / KB;   // 16

    auto stage_load = [&](int kc, int s) {
        unsigned sb = smem_u32 + s * ST_BYTES;
        {
            int row = tid >> 2, c = tid & 3;
            int mm = m0 + row;
            bool valid = (mm < n);
            int kg = kc + c * 8;
            const __nv_bfloat16 *sh, *sl;
            if (kg < 256) {
                sh = g_el_hi + (long long)mm * H + kg;
                sl = g_el_lo + (long long)mm * H + kg;
            } else {
                sh = g_er_hi + (long long)mm * H + (kg - 256);
                sl = g_er_lo + (long long)mm * H + (kg - 256);
            }
            unsigned d = sb + ST_A_HI + row * 80 + c * 16;
            cpasync16(d, sh, valid);
            cpasync16(d + (ST_A_LO - ST_A_HI), sl, valid);
        }
#pragma unroll
        for (int rep = 0; rep < 2; rep++) {
            int idx = tid + rep * NT;
            int kk = idx >> 5, c = idx & 31;
            size_t goff = (size_t)(kc + kk) * 256 + c * 8;
            unsigned d = sb + ST_W_HI + kk * 528 + c * 16;
            cpasync16(d, &g_We_hi[0][0] + goff, true);
            cpasync16(d + (ST_W_LO - ST_W_HI), &g_We_lo[0][0] + goff, true);
        }
    };

    stage_load(0, 0); CP_COMMIT();
    stage_load(KB, 1); CP_COMMIT();

    for (int ci = 0; ci < nch; ci++) {
        if (ci + 1 < nch) asm volatile("cp.async.wait_group 1;" ::: "memory");
        else              asm volatile("cp.async.wait_group 0;" ::: "memory");
        __syncthreads();
        if (ci + 2 < nch) { stage_load((ci + 2) * KB, (ci + 2) % NSTAGE); CP_COMMIT(); }

        const unsigned sb = smem_u32 + (ci % NSTAGE) * ST_BYTES;
        const unsigned as_hi_base = sb + ST_A_HI;
        const unsigned as_lo_base = sb + ST_A_LO;
        const unsigned wk_hi_base = sb + ST_W_HI;
        const unsigned wk_lo_base = sb + ST_W_LO;

#pragma unroll
        for (int ks = 0; ks < 2; ks++) {
            const int krow = ks * 16;
            unsigned ah[2][4], al[2][4];
#pragma unroll
            for (int mf = 0; mf < 2; mf++) {
                unsigned off = ((wm * 32 + mf * 16 + (lane & 15)) * APAD
                                + krow + ((lane >> 4) << 3)) * 2;
                ldsm4(ah[mf][0], ah[mf][1], ah[mf][2], ah[mf][3], as_hi_base + off);
                ldsm4(al[mf][0], al[mf][1], al[mf][2], al[mf][3], as_lo_base + off);
            }
#pragma unroll
            for (int q = 0; q < 4; q++) {
                unsigned boff = ((krow + (lane & 15)) * WPITCH
                                 + wn * 64 + q * 16 + ((lane >> 4) << 3)) * 2;
                unsigned bh[4], bl[4];
                ldsm4t(bh[0], bh[1], bh[2], bh[3], wk_hi_base + boff);
                ldsm4t(bl[0], bl[1], bl[2], bl[3], wk_lo_base + boff);
#pragma unroll
                for (int mf = 0; mf < 2; mf++)
#pragma unroll
                    for (int sub = 0; sub < 2; sub++) {
                        int f = q * 2 + sub;
                        mma16816(acc[mf][f], ah[mf], bh[sub * 2], bh[sub * 2 + 1]);
                        mma16816(acc[mf][f], ah[mf], bl[sub * 2], bl[sub * 2 + 1]);
                        mma16816(acc[mf][f], al[mf], bh[sub * 2], bh[sub * 2 + 1]);
                    }
            }
        }
    }

#pragma unroll
    for (int mf = 0; mf < 2; mf++)
#pragma unroll
        for (int rh = 0; rh < 2; rh++) {
            int m = m0 + wm * 32 + mf * 16 + rh * 8 + (lane >> 2);
            if (m >= n) continue;
#pragma unroll
            for (int f = 0; f < 8; f++) {
                int colb = wn * 64 + f * 8 + 2 * (lane & 3);
                float v0 = tanhf(acc[mf][f][rh * 2 + 0] + benc[colb]);
                float v1 = tanhf(acc[mf][f][rh * 2 + 1] + benc[colb + 1]);
                size_t o = (off + m) * (size_t)H + colb;
                __nv_bfloat16 h0 = __float2bfloat16(v0);
                __nv_bfloat16 h1 = __float2bfloat16(v1);
                g_enc_hi[o]     = h0;
                g_enc_lo[o]     = __float2bfloat16(v0 - __bfloat162float(h0));
                g_enc_hi[o + 1] = h1;
                g_enc_lo[o + 1] = __float2bfloat16(v1 - __bfloat162float(h1));
                if (outp != nullptr && m == 0) {
                    outp[colb] = v0;
                    outp[colb + 1] = v1;
                }
            }
        }
}

extern "C" void kernel_launch(void* const* d_in, const int* in_sizes, int n_in,
                              void* d_out, int out_size)
{
    const float* node_init = (const float*)d_in[0];
    const float* Wih_l = (const float*)d_in[1];
    const float* Whh_l = (const float*)d_in[2];
    const float* bih_l = (const float*)d_in[3];
    const float* bhh_l = (const float*)d_in[4];
    const float* Wih_r = (const float*)d_in[5];
    const float* Whh_r = (const float*)d_in[6];
    const float* bih_r = (const float*)d_in[7];
    const float* bhh_r = (const float*)d_in[8];
    const float* Wenc  = (const float*)d_in[9];
    const float* benc  = (const float*)d_in[10];
    float* out = (float*)d_out;

    cudaFuncSetAttribute(lstm_step_kernel, cudaFuncAttributeMaxDynamicSharedMemorySize, SMEM_BYTES);
    cudaFuncSetAttribute(enc_kernel,       cudaFuncAttributeMaxDynamicSharedMemorySize, SMEM_BYTES);

    // prep: split node_init + weights
    {
        int total = N_TOTAL * H + 2 * 512 * 1024 + 512 * 256 + 2048;
        prep_kernel<<<(total + 255) / 256, 256>>>(
            node_init, Wih_l, Whh_l, bih_l, bhh_l, Wih_r, Whh_r, bih_r, bhh_r, Wenc);
    }

    static const int       SZ[7]  = {1, 8, 64, 512, 4096, 32768, 262144};
    static const long long OFF[7] = {0, 1, 9, 73, 585, 4681, 37449};

    // ---- leaf level d=6: T=1 LSTM (h0=c0=0, K=256) ----
    {
        int n = SZ[6]; long long off = OFF[6];
        dim3 g((n + BMM - 1) / BMM, 4, 2);
        lstm_step_kernel<<<g, NT, SMEM_BYTES>>>(
            n, /*first=*/1, /*last=*/1, /*pp=*/0, /*Ktot=*/256,
            /*xl*/ 0, off, 1, /*xr*/ 0, off, 1);
        dim3 ge((n + BMM - 1) / BMM, 1, 1);
        enc_kernel<<<ge, NT, SMEM_BYTES>>>(benc, n, off, nullptr);
    }

    // ---- levels d=5..0: T=5 chains ----
    for (int d = 5; d >= 0; d--) {
        int n = SZ[d];
        long long off = OFF[d], coff = OFF[d + 1];
        dim3 g((n + BMM - 1) / BMM, 4, 2);
        dim3 ge((n + BMM - 1) / BMM, 1, 1);
        for (int t = 0; t < 5; t++) {
            int first = (t == 0), last = (t == 4), pp = (t & 1) ^ 1;
            int Ktot = first ? 256 : 512;
            // left chain:  t=0..3 -> child (3-t), t=4 -> own
            int xsl, xstr_l; long long xol;
            if (t < 4) { xsl = 1; xol = coff + (3 - t); xstr_l = 8; }
            else       { xsl = 0; xol = off;            xstr_l = 1; }
            // right chain: t=0 -> own, t=1..4 -> child (3+t)
            int xsr, xstr_r; long long xorr;
            if (t == 0) { xsr = 0; xorr = off;            xstr_r = 1; }
            else        { xsr = 1; xorr = coff + (3 + t); xstr_r = 8; }
            lstm_step_kernel<<<g, NT, SMEM_BYTES>>>(
                n, first, last, pp, Ktot, xsl, xol, xstr_l, xsr, xorr, xstr_r);
        }
        enc_kernel<<<ge, NT, SMEM_BYTES>>>(benc, n, off, (d == 0) ? out : nullptr);
    }
}